// round 4
// baseline (speedup 1.0000x reference)
#include <cuda_runtime.h>

#define NQ   4
#define DIM  16
#define NH   8
#define NL   2
#define EMB  32
#define NT3  81   // 3^4 basis terms per head
#define BLK  128  // threads per block, 2 tokens per thread

typedef unsigned long long u64;

// Per-head Fourier coefficients: [h][t] -> float4 (ev index 0..3), 16B aligned
__device__ float4 g_C4[NH * NT3];

// ---- packed f32x2 helpers -------------------------------------------------
#define FMAX2(d, a, b, c) \
    asm("fma.rn.f32x2 %0, %1, %2, %3;" : "=l"(d) : "l"(a), "l"(b), "l"(c))
#define MUL2(d, a, b) \
    asm("mul.rn.f32x2 %0, %1, %2;" : "=l"(d) : "l"(a), "l"(b))
#define PACK2(d, lo, hi) \
    asm("mov.b64 %0, {%1, %2};" : "=l"(d) : "f"(lo), "f"(hi))
#define UNPACK2(lo, hi, d) \
    asm("mov.b64 {%0, %1}, %2;" : "=f"(lo), "=f"(hi) : "l"(d))

// ---------------------------------------------------------------------------
// Setup kernel: shuffle-parallel simulation of the fixed per-head unitary.
// 8 blocks x 256 threads; thread (k,m) holds amplitude <m|U|k>.
// ---------------------------------------------------------------------------
__global__ void qc_setup_kernel(const float* __restrict__ params) {
    __shared__ float Vre[DIM][DIM + 1];
    __shared__ float Vim[DIM][DIM + 1];
    __shared__ float Msh[DIM * DIM][4];

    const int h   = blockIdx.x;
    const int tid = threadIdx.x;     // 0..255
    const int m   = tid & 15;        // amplitude index
    const int k   = tid >> 4;        // input basis state

    float re = (k == m) ? 1.f : 0.f;
    float im = 0.f;

    const float* p = params + h * NL * NQ * 3;

    #pragma unroll
    for (int l = 0; l < NL; l++) {
        #pragma unroll
        for (int q = 0; q < NQ; q++) {
            const int mask = 8 >> q;   // qubit 0 = MSB
            float th, c, s, r1, i1;

            // RX
            th = p[(l * NQ + q) * 3 + 0];
            c = cosf(0.5f * th); s = sinf(0.5f * th);
            r1 = __shfl_xor_sync(0xffffffffu, re, mask);
            i1 = __shfl_xor_sync(0xffffffffu, im, mask);
            re = c * re + s * i1;
            im = c * im - s * r1;

            // RY
            th = p[(l * NQ + q) * 3 + 1];
            c = cosf(0.5f * th); s = sinf(0.5f * th);
            r1 = __shfl_xor_sync(0xffffffffu, re, mask);
            i1 = __shfl_xor_sync(0xffffffffu, im, mask);
            {
                const float sgn = (m & mask) ? s : -s;
                re = c * re + sgn * r1;
                im = c * im + sgn * i1;
            }

            // RZ
            th = p[(l * NQ + q) * 3 + 2];
            c = cosf(0.5f * th); s = sinf(0.5f * th);
            {
                const float sg = (m & mask) ? s : -s;
                const float r = re, i = im;
                re = c * r - sg * i;
                im = c * i + sg * r;
            }
        }
        // CNOT chain
        const int cm[4] = {8, 4, 2, 1};
        const int tm[4] = {4, 2, 1, 8};
        #pragma unroll
        for (int e = 0; e < 4; e++) {
            const float r1 = __shfl_xor_sync(0xffffffffu, re, tm[e]);
            const float i1 = __shfl_xor_sync(0xffffffffu, im, tm[e]);
            if (m & cm[e]) { re = r1; im = i1; }
        }
    }

    Vre[k][m] = re;
    Vim[k][m] = im;
    __syncthreads();

    // M_i[k,l] = sum_m z_i(m) Re(conj(V[m,k]) V[m,l])
    {
        const int kk = tid >> 4;
        const int ll = tid & 15;
        float P[DIM];
        float tot = 0.f;
        #pragma unroll
        for (int mm = 0; mm < DIM; mm++) {
            P[mm] = Vre[kk][mm] * Vre[ll][mm] + Vim[kk][mm] * Vim[ll][mm];
            tot += P[mm];
        }
        #pragma unroll
        for (int i = 0; i < 4; i++) {
            float sub = 0.f;
            #pragma unroll
            for (int mm = 0; mm < DIM; mm++)
                if ((mm >> (3 - i)) & 1) sub += P[mm];
            Msh[tid][i] = tot - 2.f * sub;
        }
    }
    __syncthreads();

    // Expand into the 81-term basis via Msh lookups.
    for (int idx = tid; idx < 4 * NT3; idx += blockDim.x) {
        const int i = idx / NT3;
        const int t = idx % NT3;
        const int tq[4] = { t / 27, (t / 9) % 3, (t / 3) % 3, t % 3 };

        float acc = 0.f;
        for (int b = 0; b < 16; b++) {
            int kk = 0, ll = 0;
            float sgn = 1.f / 16.f;
            #pragma unroll
            for (int q = 0; q < 4; q++) {
                const int bq = (b >> q) & 1;
                const int sh = 3 - q;
                if (tq[q] == 2) {
                    kk |= bq << sh; ll |= (1 - bq) << sh;
                } else {
                    kk |= bq << sh; ll |= bq << sh;
                    if (tq[q] == 1 && bq) sgn = -sgn;
                }
            }
            acc += sgn * Msh[kk * DIM + ll][i];
        }
        ((float*)g_C4)[(h * NT3 + t) * 4 + i] = acc;
    }
}

// ---------------------------------------------------------------------------
// Main kernel: 2 tokens/thread, fully packed f32x2 math.
// The trig basis is stored pre-duplicated as (v,v) u64, so the product chain
// runs in mul.f32x2 and the inner loop has ZERO pack movs: 1 LDS.128 +
// <=1 mul + 4 FMAX2 per term (both tokens).
// ---------------------------------------------------------------------------
__global__ __launch_bounds__(BLK, 4) void qc_main_kernel(
    const float*  __restrict__ x,
    const float*  __restrict__ W,      // [EMB][NH*NQ] row-major
    const float*  __restrict__ bias,   // [EMB]
    float*        __restrict__ out,
    int ntok)
{
    __shared__ ulonglong2 Cs[NH * NT3];     // (c0,c1),(c2,c3) packed pairs
    __shared__ ulonglong2 Wq[NH * 4 * 8];   // [h][i][k]: ((W[4k],W[4k+1]),(W[4k+2],W[4k+3])) col 4h+i
    __shared__ u64        bs2[16];          // (b[2jp], b[2jp+1])

    const int tid = threadIdx.x;
    for (int i = tid; i < NH * NT3; i += BLK)
        Cs[i] = reinterpret_cast<const ulonglong2*>(g_C4)[i];
    for (int i = tid; i < NH * 4 * 8; i += BLK) {
        const int k = i & 7;
        const int c = i >> 3;     // c = 4h + i_ev  (since (h*4+i) = i>>3)
        u64 lo, hi;
        PACK2(lo, W[(4 * k + 0) * EMB + c], W[(4 * k + 1) * EMB + c]);
        PACK2(hi, W[(4 * k + 2) * EMB + c], W[(4 * k + 3) * EMB + c]);
        Wq[i] = make_ulonglong2(lo, hi);
    }
    if (tid < 16) {
        u64 v;
        PACK2(v, bias[2 * tid], bias[2 * tid + 1]);
        bs2[tid] = v;
    }
    __syncthreads();

    const int tokA = blockIdx.x * (BLK * 2) + tid;
    const int tokB = tokA + BLK;
    const bool okA = tokA < ntok, okB = tokB < ntok;

    u64 accA[16], accB[16];
    #pragma unroll
    for (int jp = 0; jp < 16; jp++) { accA[jp] = bs2[jp]; accB[jp] = bs2[jp]; }

    u64 one2;
    PACK2(one2, 1.0f, 1.0f);

    const float4* xp4 = reinterpret_cast<const float4*>(x);

    #pragma unroll 1
    for (int h = 0; h < NH; h++) {
        const ulonglong2* Ch = Cs + h * NT3;

        float4 xa = okA ? xp4[(size_t)tokA * NH + h] : make_float4(0.f, 0.f, 0.f, 0.f);
        float4 xb = okB ? xp4[(size_t)tokB * NH + h] : make_float4(0.f, 0.f, 0.f, 0.f);

        // dup-packed trig basis: Ad[q][0]=(cos,cos), Ad[q][1]=(sin,sin)
        u64 Ad[4][2], Bd[4][2];
        {
            float c, s;
            __sincosf(xa.x, &s, &c); PACK2(Ad[0][0], c, c); PACK2(Ad[0][1], s, s);
            __sincosf(xa.y, &s, &c); PACK2(Ad[1][0], c, c); PACK2(Ad[1][1], s, s);
            __sincosf(xa.z, &s, &c); PACK2(Ad[2][0], c, c); PACK2(Ad[2][1], s, s);
            __sincosf(xa.w, &s, &c); PACK2(Ad[3][0], c, c); PACK2(Ad[3][1], s, s);
            __sincosf(xb.x, &s, &c); PACK2(Bd[0][0], c, c); PACK2(Bd[0][1], s, s);
            __sincosf(xb.y, &s, &c); PACK2(Bd[1][0], c, c); PACK2(Bd[1][1], s, s);
            __sincosf(xb.z, &s, &c); PACK2(Bd[2][0], c, c); PACK2(Bd[2][1], s, s);
            __sincosf(xb.w, &s, &c); PACK2(Bd[3][0], c, c); PACK2(Bd[3][1], s, s);
        }

        u64 evA01 = 0ull, evA23 = 0ull, evB01 = 0ull, evB23 = 0ull;

        int term = 0;
        #pragma unroll
        for (int a = 0; a < 3; a++) {
            u64 pA0 = 0, pB0 = 0;
            if (a > 0) { pA0 = Ad[0][a - 1]; pB0 = Bd[0][a - 1]; }
            #pragma unroll
            for (int b = 0; b < 3; b++) {
                u64 pA1 = 0, pB1 = 0;
                if (a == 0 && b > 0)      { pA1 = Ad[1][b - 1]; pB1 = Bd[1][b - 1]; }
                else if (a > 0 && b == 0) { pA1 = pA0;          pB1 = pB0; }
                else if (a > 0 && b > 0)  { MUL2(pA1, pA0, Ad[1][b - 1]);
                                            MUL2(pB1, pB0, Bd[1][b - 1]); }
                #pragma unroll
                for (int c = 0; c < 3; c++) {
                    const bool v2 = (a | b) != 0;
                    u64 pA2 = 0, pB2 = 0;
                    if (!v2 && c > 0)     { pA2 = Ad[2][c - 1]; pB2 = Bd[2][c - 1]; }
                    else if (v2 && c == 0){ pA2 = pA1;          pB2 = pB1; }
                    else if (v2 && c > 0) { MUL2(pA2, pA1, Ad[2][c - 1]);
                                            MUL2(pB2, pB1, Bd[2][c - 1]); }
                    #pragma unroll
                    for (int d = 0; d < 3; d++) {
                        const bool v3 = (a | b | c) != 0;
                        u64 phA, phB;
                        if (!v3 && d == 0)      { phA = one2;            phB = one2; }
                        else if (!v3)           { phA = Ad[3][d - 1];    phB = Bd[3][d - 1]; }
                        else if (d == 0)        { phA = pA2;             phB = pB2; }
                        else                    { MUL2(phA, pA2, Ad[3][d - 1]);
                                                  MUL2(phB, pB2, Bd[3][d - 1]); }
                        const ulonglong2 cc = Ch[term++];
                        FMAX2(evA01, cc.x, phA, evA01);
                        FMAX2(evA23, cc.y, phA, evA23);
                        FMAX2(evB01, cc.x, phB, evB01);
                        FMAX2(evB23, cc.y, phB, evB23);
                    }
                }
            }
        }

        // Fold into j-packed accumulators; W loads shared by both tokens.
        u64 dA[4], dB[4];
        {
            float e0, e1, e2, e3;
            UNPACK2(e0, e1, evA01); UNPACK2(e2, e3, evA23);
            PACK2(dA[0], e0, e0); PACK2(dA[1], e1, e1);
            PACK2(dA[2], e2, e2); PACK2(dA[3], e3, e3);
            UNPACK2(e0, e1, evB01); UNPACK2(e2, e3, evB23);
            PACK2(dB[0], e0, e0); PACK2(dB[1], e1, e1);
            PACK2(dB[2], e2, e2); PACK2(dB[3], e3, e3);
        }
        const ulonglong2* Wh = Wq + h * 32;
        #pragma unroll
        for (int i = 0; i < 4; i++) {
            const u64 ai = dA[i], bi = dB[i];
            #pragma unroll
            for (int k = 0; k < 8; k++) {
                const ulonglong2 wd = Wh[i * 8 + k];
                FMAX2(accA[2 * k],     wd.x, ai, accA[2 * k]);
                FMAX2(accA[2 * k + 1], wd.y, ai, accA[2 * k + 1]);
                FMAX2(accB[2 * k],     wd.x, bi, accB[2 * k]);
                FMAX2(accB[2 * k + 1], wd.y, bi, accB[2 * k + 1]);
            }
        }
    }

    if (okA) {
        ulonglong2* op = reinterpret_cast<ulonglong2*>(out + (size_t)tokA * EMB);
        #pragma unroll
        for (int jj = 0; jj < 8; jj++)
            op[jj] = make_ulonglong2(accA[2 * jj], accA[2 * jj + 1]);
    }
    if (okB) {
        ulonglong2* op = reinterpret_cast<ulonglong2*>(out + (size_t)tokB * EMB);
        #pragma unroll
        for (int jj = 0; jj < 8; jj++)
            op[jj] = make_ulonglong2(accB[2 * jj], accB[2 * jj + 1]);
    }
}

// ---------------------------------------------------------------------------
extern "C" void kernel_launch(void* const* d_in, const int* in_sizes, int n_in,
                              void* d_out, int out_size) {
    const float* x      = (const float*)d_in[0];
    const float* params = (const float*)d_in[1];
    const float* W      = (const float*)d_in[2];
    const float* b      = (const float*)d_in[3];
    float* out = (float*)d_out;

    const int ntok = in_sizes[0] / EMB;

    qc_setup_kernel<<<NH, 256>>>(params);

    const int tok_per_block = BLK * 2;
    const int blocks = (ntok + tok_per_block - 1) / tok_per_block;
    qc_main_kernel<<<blocks, BLK>>>(x, W, b, out, ntok);
}